// round 1
// baseline (speedup 1.0000x reference)
#include <cuda_runtime.h>
#include <cstdint>

#define S_  2048
#define B_  2
#define C_  512
#define H_  8
#define CC_ 64
#define M_  (S_*B_)      // 4096
#define K3C_ (3*C_)      // 1536

// Scratch (static device globals — no dynamic allocation allowed)
__device__ float g_qkv[(size_t)M_ * K3C_];   // (s*B+b, 3C)
__device__ float g_attn[(size_t)M_ * C_];    // (s*B+b, C)

// ---------------------------------------------------------------------------
// Tiled NT GEMM: out[m][n] = sum_k (A[m][k] (+ A2[m][k])) * W[n][k] + bias[n]
// BM=BN=64, BK=16, 256 threads, 4x4 micro-tile per thread.
// Assumes Mdim%64==0, Ndim%64==0, Kdim%16==0 (true for all our shapes).
// ---------------------------------------------------------------------------
template<bool ADD2>
__global__ void __launch_bounds__(256, 4)
gemm_nt(const float* __restrict__ A, const float* __restrict__ A2,
        const float* __restrict__ W, const float* __restrict__ bias,
        float* __restrict__ out, int Mdim, int Ndim, int Kdim)
{
    __shared__ float As[16][64];
    __shared__ float Bs[16][64];

    const int tid = threadIdx.x;
    const int tx = tid & 15;
    const int ty = tid >> 4;
    const int m0 = blockIdx.y * 64;
    const int n0 = blockIdx.x * 64;

    float acc[4][4] = {};

    for (int k0 = 0; k0 < Kdim; k0 += 16) {
        #pragma unroll
        for (int i = tid; i < 64 * 16; i += 256) {
            int r  = i >> 4;
            int kk = i & 15;
            float a = A[(size_t)(m0 + r) * Kdim + k0 + kk];
            if (ADD2) a += A2[(size_t)(m0 + r) * Kdim + k0 + kk];
            As[kk][r] = a;
            Bs[kk][r] = W[(size_t)(n0 + r) * Kdim + k0 + kk];
        }
        __syncthreads();

        #pragma unroll
        for (int kk = 0; kk < 16; kk++) {
            float4 a4 = *(const float4*)&As[kk][ty * 4];
            float4 b4 = *(const float4*)&Bs[kk][tx * 4];
            float a[4] = {a4.x, a4.y, a4.z, a4.w};
            float b[4] = {b4.x, b4.y, b4.z, b4.w};
            #pragma unroll
            for (int i = 0; i < 4; i++)
                #pragma unroll
                for (int j = 0; j < 4; j++)
                    acc[i][j] += a[i] * b[j];
        }
        __syncthreads();
    }

    #pragma unroll
    for (int i = 0; i < 4; i++) {
        int mrow = m0 + ty * 4 + i;
        #pragma unroll
        for (int j = 0; j < 4; j++) {
            int ncol = n0 + tx * 4 + j;
            out[(size_t)mrow * Ndim + ncol] = acc[i][j] + bias[ncol];
        }
    }
}

// ---------------------------------------------------------------------------
// Causal attention, fp32. One warp per query row; 4 queries per block share
// K/V tiles (32 t-positions x 64 dims). Online softmax; PV via shfl broadcast.
// Reads g_qkv (q at +0, k at +C, v at +2C within the 3C row), writes g_attn.
// ---------------------------------------------------------------------------
#define TPAD 68  // row stride (floats) for K/V tiles: 16B-aligned rows, conflict-free

__global__ void __launch_bounds__(128)
attn_kernel()
{
    const int warp = threadIdx.x >> 5;
    const int lane = threadIdx.x & 31;
    const int qbase = blockIdx.x * 4;
    const int b = blockIdx.y;
    const int h = blockIdx.z;
    const int q = qbase + warp;

    __shared__ float ks[32 * TPAD];
    __shared__ float vs[32 * TPAD];
    __shared__ float qs[4][64];

    // load this warp's query row into shared (broadcast source for the dot)
    {
        const float* qptr = g_qkv + (size_t)(q * B_ + b) * K3C_ + h * CC_;
        qs[warp][lane]      = qptr[lane];
        qs[warp][lane + 32] = qptr[lane + 32];
    }

    float m  = -1e30f;
    float l  = 0.0f;      // per-lane partial; reduced at the end
    float o0 = 0.0f, o1 = 0.0f;

    const int qmax = qbase + 3;  // all warps run the same tile count (4 | 32)

    for (int t0 = 0; t0 <= qmax; t0 += 32) {
        __syncthreads();
        // cooperative K/V tile load: 32 rows x 64 cols each
        for (int i = threadIdx.x; i < 32 * 64; i += 128) {
            int r = i >> 6;
            int c = i & 63;
            size_t off = ((size_t)(t0 + r) * B_ + b) * K3C_ + h * CC_ + c;
            ks[r * TPAD + c] = g_qkv[off + C_];
            vs[r * TPAD + c] = g_qkv[off + 2 * C_];
        }
        __syncthreads();

        // score: lane j handles t = t0 + j
        float s = 0.0f;
        const float4* q4 = (const float4*)qs[warp];
        const float4* k4 = (const float4*)(ks + lane * TPAD);
        #pragma unroll
        for (int c = 0; c < 16; c++) {
            float4 qv = q4[c];
            float4 kv = k4[c];
            s += qv.x * kv.x + qv.y * kv.y + qv.z * kv.z + qv.w * kv.w;
        }
        s *= 0.125f;  // 1/sqrt(64)
        int t = t0 + lane;
        if (t > q) s = -1e30f;

        // online softmax update (warp-uniform max)
        float tmax = s;
        #pragma unroll
        for (int off = 16; off; off >>= 1)
            tmax = fmaxf(tmax, __shfl_xor_sync(0xffffffffu, tmax, off));
        float mnew  = fmaxf(m, tmax);
        float scale = __expf(m - mnew);
        float e     = __expf(s - mnew);
        l = l * scale + e;
        o0 *= scale;
        o1 *= scale;

        // PV: broadcast p_t across the warp; lane owns output dims lane, lane+32
        #pragma unroll
        for (int j = 0; j < 32; j++) {
            float p = __shfl_sync(0xffffffffu, e, j);
            o0 += p * vs[j * TPAD + lane];
            o1 += p * vs[j * TPAD + lane + 32];
        }
        m = mnew;
    }

    // reduce l across the warp, normalize, store
    float lt = l;
    #pragma unroll
    for (int off = 16; off; off >>= 1)
        lt += __shfl_xor_sync(0xffffffffu, lt, off);
    float inv = 1.0f / lt;

    float* optr = g_attn + (size_t)(q * B_ + b) * C_ + h * CC_;
    optr[lane]      = o0 * inv;
    optr[lane + 32] = o1 * inv;
}

// ---------------------------------------------------------------------------
// Inputs (metadata order): x, pe, content_mask, pad, Wqkv, bqkv, Wc, bc
// content_mask is strict-causal (t > s) -> applied analytically; pad unused.
// ---------------------------------------------------------------------------
extern "C" void kernel_launch(void* const* d_in, const int* in_sizes, int n_in,
                              void* d_out, int out_size)
{
    const float* x    = (const float*)d_in[0];
    const float* pe   = (const float*)d_in[1];
    const float* Wqkv = (const float*)d_in[4];
    const float* bqkv = (const float*)d_in[5];
    const float* Wc   = (const float*)d_in[6];
    const float* bc   = (const float*)d_in[7];
    float* out = (float*)d_out;

    float *qkv, *attn;
    cudaGetSymbolAddress((void**)&qkv,  g_qkv);
    cudaGetSymbolAddress((void**)&attn, g_attn);

    // 1) qkv = (x + pe) @ Wqkv^T + bqkv     (4096 x 1536 x 512)
    gemm_nt<true><<<dim3(K3C_ / 64, M_ / 64), 256>>>(
        x, pe, Wqkv, bqkv, qkv, M_, K3C_, C_);

    // 2) causal attention -> g_attn
    attn_kernel<<<dim3(S_ / 4, B_, H_), 128>>>();

    // 3) out = attn @ Wc^T + bc             (4096 x 512 x 512)
    gemm_nt<false><<<dim3(C_ / 64, M_ / 64), 256>>>(
        attn, nullptr, Wc, bc, out, M_, C_, C_);
}

// round 3
// speedup vs baseline: 2.7800x; 2.7800x over previous
#include <cuda_runtime.h>
#include <cstdint>

#define S_   2048
#define B_   2
#define C_   512
#define H_   8
#define CC_  64
#define M_   (S_*B_)      // 4096
#define K3C_ (3*C_)       // 1536

// Scratch (static device globals — no dynamic allocation allowed)
__device__ float g_qkv[(size_t)M_ * K3C_];   // (s*B+b, 3C)
__device__ float g_attn[(size_t)M_ * C_];    // (s*B+b, C)

// ============================================================================
// tf32 helpers (portable PTX — no sm_103a-only instructions)
// ============================================================================
__device__ __forceinline__ uint32_t f2tf(float f) {
    uint32_t u;
    asm("cvt.rna.tf32.f32 %0, %1;" : "=r"(u) : "f"(f));
    return u;
}

__device__ __forceinline__ void mma_tf32(float c[4], const uint32_t a[4],
                                         const uint32_t b[2]) {
    asm volatile(
        "mma.sync.aligned.m16n8k8.row.col.f32.tf32.tf32.f32 "
        "{%0,%1,%2,%3}, {%4,%5,%6,%7}, {%8,%9}, {%0,%1,%2,%3};"
        : "+f"(c[0]), "+f"(c[1]), "+f"(c[2]), "+f"(c[3])
        : "r"(a[0]), "r"(a[1]), "r"(a[2]), "r"(a[3]), "r"(b[0]), "r"(b[1]));
}

// ============================================================================
// HMMA tf32 GEMM (NT): out[m][n] = sum_k (A[m][k](+A2[m][k])) * W[n][k] + b[n]
// BM=128, BN=128, BK=32. 8 warps as 2(m) x 4(n); warp tile 64x32 =
// 4x4 m16n8k8 tiles. Smem stride 36 floats -> conflict-free fragment LDS.
// All dims assumed %128/%32 (true for our shapes).
// ============================================================================
#define GBM 128
#define GBN 128
#define GBK 32
#define GST 36   // smem row stride in floats

template<bool ADD2>
__global__ void __launch_bounds__(256, 2)
gemm_mma(const float* __restrict__ A, const float* __restrict__ A2,
         const float* __restrict__ W, const float* __restrict__ bias,
         float* __restrict__ out, int Mdim, int Ndim, int Kdim)
{
    __shared__ uint32_t As[GBM * GST];
    __shared__ uint32_t Bs[GBN * GST];

    const int tid  = threadIdx.x;
    const int warp = tid >> 5;
    const int lane = tid & 31;
    const int g    = lane >> 2;    // 0..7
    const int tig  = lane & 3;     // 0..3
    const int wm   = warp & 1;     // 2 warps along m
    const int wn   = warp >> 1;    // 4 warps along n
    const int m0 = blockIdx.y * GBM;
    const int n0 = blockIdx.x * GBN;

    float acc[4][4][4] = {};       // [mi][nj][reg]

    for (int k0 = 0; k0 < Kdim; k0 += GBK) {
        __syncthreads();
        // Stage tiles: 128 rows x 32 floats each (8 float4 per row).
        #pragma unroll
        for (int t = 0; t < 4; t++) {
            int idx = tid + t * 256;       // 0..1023
            int r = idx >> 3, q = idx & 7;
            float4 va = *(const float4*)&A[(size_t)(m0 + r) * Kdim + k0 + q * 4];
            if (ADD2) {
                float4 v2 = *(const float4*)&A2[(size_t)(m0 + r) * Kdim + k0 + q * 4];
                va.x += v2.x; va.y += v2.y; va.z += v2.z; va.w += v2.w;
            }
            uint4 ua = make_uint4(f2tf(va.x), f2tf(va.y), f2tf(va.z), f2tf(va.w));
            *(uint4*)&As[r * GST + q * 4] = ua;

            float4 vb = *(const float4*)&W[(size_t)(n0 + r) * Kdim + k0 + q * 4];
            uint4 ub = make_uint4(f2tf(vb.x), f2tf(vb.y), f2tf(vb.z), f2tf(vb.w));
            *(uint4*)&Bs[r * GST + q * 4] = ub;
        }
        __syncthreads();

        #pragma unroll
        for (int ks = 0; ks < 4; ks++) {
            const int kb = ks * 8;
            uint32_t a[4][4], b[4][2];
            #pragma unroll
            for (int i = 0; i < 4; i++) {
                const int row = wm * 64 + i * 16;
                a[i][0] = As[(row + g)     * GST + kb + tig];
                a[i][1] = As[(row + g + 8) * GST + kb + tig];
                a[i][2] = As[(row + g)     * GST + kb + tig + 4];
                a[i][3] = As[(row + g + 8) * GST + kb + tig + 4];
            }
            #pragma unroll
            for (int j = 0; j < 4; j++) {
                const int col = wn * 32 + j * 8;
                b[j][0] = Bs[(col + g) * GST + kb + tig];
                b[j][1] = Bs[(col + g) * GST + kb + tig + 4];
            }
            #pragma unroll
            for (int i = 0; i < 4; i++)
                #pragma unroll
                for (int j = 0; j < 4; j++)
                    mma_tf32(acc[i][j], a[i], b[j]);
        }
    }

    // Epilogue: c0,c1 at (row=g, col=2*tig, 2*tig+1); c2,c3 at row g+8.
    #pragma unroll
    for (int i = 0; i < 4; i++) {
        const int row = m0 + wm * 64 + i * 16 + g;
        #pragma unroll
        for (int j = 0; j < 4; j++) {
            const int col = n0 + wn * 32 + j * 8 + 2 * tig;
            float2 bv = *(const float2*)&bias[col];
            float2 o0 = make_float2(acc[i][j][0] + bv.x, acc[i][j][1] + bv.y);
            float2 o1 = make_float2(acc[i][j][2] + bv.x, acc[i][j][3] + bv.y);
            *(float2*)&out[(size_t)row * Ndim + col]       = o0;
            *(float2*)&out[(size_t)(row + 8) * Ndim + col] = o1;
        }
    }
}

// ============================================================================
// Causal attention, fp32 SIMT. 256 threads = 8 warps x 4 queries/warp = 32
// queries per block sharing each 32x64 K/V tile. Online softmax; PV via
// smem-staged float4 probabilities (broadcast LDS instead of shfl).
// ============================================================================
#define TPAD 68  // 68 floats = 272B rows: 16B-aligned, conflict-free LDS.128

#define SOFTMAX_STEP(S, MV, LV, OA, OB, EV)                                    \
    {                                                                          \
        float tm = S;                                                          \
        tm = fmaxf(tm, __shfl_xor_sync(0xffffffffu, tm, 16));                  \
        tm = fmaxf(tm, __shfl_xor_sync(0xffffffffu, tm, 8));                   \
        tm = fmaxf(tm, __shfl_xor_sync(0xffffffffu, tm, 4));                   \
        tm = fmaxf(tm, __shfl_xor_sync(0xffffffffu, tm, 2));                   \
        tm = fmaxf(tm, __shfl_xor_sync(0xffffffffu, tm, 1));                   \
        float mn = fmaxf(MV, tm);                                              \
        float sc = __expf(MV - mn);                                            \
        EV = __expf(S - mn);                                                   \
        LV = LV * sc + EV;                                                     \
        OA *= sc; OB *= sc;                                                    \
        MV = mn;                                                               \
    }

__global__ void __launch_bounds__(256)
attn_kernel()
{
    const int warp = threadIdx.x >> 5;
    const int lane = threadIdx.x & 31;
    // heavy (large-q) blocks first to hide the serial tail
    const int qblk = ((int)gridDim.x - 1 - (int)blockIdx.x) * 32;
    const int b = blockIdx.y;
    const int h = blockIdx.z;
    const int q0 = qblk + warp * 4;

    __shared__ float ks[32 * TPAD];
    __shared__ float vs[32 * TPAD];
    __shared__ float qs[8][4][TPAD];
    __shared__ float4 ps[8][32];

    // load 32 query rows (transposed into per-warp slots)
    for (int i = threadIdx.x; i < 32 * 64; i += 256) {
        int r = i >> 6, c = i & 63;
        qs[r >> 2][r & 3][c] =
            g_qkv[((size_t)(qblk + r) * B_ + b) * K3C_ + h * CC_ + c];
    }

    float m0v = -1e30f, m1v = -1e30f, m2v = -1e30f, m3v = -1e30f;
    float l0 = 0, l1 = 0, l2 = 0, l3 = 0;
    float o00 = 0, o01 = 0, o10 = 0, o11 = 0;
    float o20 = 0, o21 = 0, o30 = 0, o31 = 0;

    const int qmax_blk = qblk + 31;
    const int myqmax = q0 + 3;

    for (int t0 = 0; t0 <= qmax_blk; t0 += 32) {
        __syncthreads();
        for (int i = threadIdx.x; i < 32 * 64; i += 256) {
            int r = i >> 6, c = i & 63;
            size_t off = ((size_t)(t0 + r) * B_ + b) * K3C_ + h * CC_ + c;
            ks[r * TPAD + c] = g_qkv[off + C_];
            vs[r * TPAD + c] = g_qkv[off + 2 * C_];
        }
        __syncthreads();
        if (t0 > myqmax) continue;

        // scores: lane j handles t = t0 + j, for 4 queries (K row reused)
        float s0 = 0, s1 = 0, s2 = 0, s3 = 0;
        {
            const float4* k4 = (const float4*)(ks + lane * TPAD);
            const float4* a0 = (const float4*)qs[warp][0];
            const float4* a1 = (const float4*)qs[warp][1];
            const float4* a2 = (const float4*)qs[warp][2];
            const float4* a3 = (const float4*)qs[warp][3];
            #pragma unroll
            for (int c = 0; c < 16; c++) {
                float4 kv = k4[c];
                float4 v;
                v = a0[c]; s0 += v.x*kv.x + v.y*kv.y + v.z*kv.z + v.w*kv.w;
                v = a1[c]; s1 += v.x*kv.x + v.y*kv.y + v.z*kv.z + v.w*kv.w;
                v = a2[c]; s2 += v.x*kv.x + v.y*kv.y + v.z*kv.z + v.w*kv.w;
                v = a3[c]; s3 += v.x*kv.x + v.y*kv.y + v.z*kv.z + v.w*kv.w;
            }
        }
        const int t = t0 + lane;
        s0 = (t <= q0 + 0) ? s0 * 0.125f : -1e30f;
        s1 = (t <= q0 + 1) ? s1 * 0.125f : -1e30f;
        s2 = (t <= q0 + 2) ? s2 * 0.125f : -1e30f;
        s3 = (t <= q0 + 3) ? s3 * 0.125f : -1e30f;

        float e0, e1, e2, e3;
        SOFTMAX_STEP(s0, m0v, l0, o00, o01, e0);
        SOFTMAX_STEP(s1, m1v, l1, o10, o11, e1);
        SOFTMAX_STEP(s2, m2v, l2, o20, o21, e2);
        SOFTMAX_STEP(s3, m3v, l3, o30, o31, e3);

        ps[warp][lane] = make_float4(e0, e1, e2, e3);
        __syncwarp();

        const float4* pp = ps[warp];
        #pragma unroll
        for (int j = 0; j < 32; j++) {
            float4 p = pp[j];                       // broadcast
            float v0 = vs[j * TPAD + lane];
            float v1 = vs[j * TPAD + lane + 32];
            o00 += p.x * v0;  o01 += p.x * v1;
            o10 += p.y * v0;  o11 += p.y * v1;
            o20 += p.z * v0;  o21 += p.z * v1;
            o30 += p.w * v0;  o31 += p.w * v1;
        }
        __syncwarp();
    }

    // final: reduce l per query, normalize, store
    #pragma unroll
    for (int qi = 0; qi < 4; qi++) {
        float lv = (qi == 0) ? l0 : (qi == 1) ? l1 : (qi == 2) ? l2 : l3;
        float oa = (qi == 0) ? o00 : (qi == 1) ? o10 : (qi == 2) ? o20 : o30;
        float ob = (qi == 0) ? o01 : (qi == 1) ? o11 : (qi == 2) ? o21 : o31;
        #pragma unroll
        for (int off = 16; off; off >>= 1)
            lv += __shfl_xor_sync(0xffffffffu, lv, off);
        float inv = 1.0f / lv;
        float* optr = g_attn + ((size_t)(q0 + qi) * B_ + b) * C_ + h * CC_;
        optr[lane]      = oa * inv;
        optr[lane + 32] = ob * inv;
    }
}

// ============================================================================
// Inputs (metadata order): x, pe, content_mask, pad, Wqkv, bqkv, Wc, bc
// content_mask is strict-causal (t > s) -> applied analytically; pad unused.
// ============================================================================
extern "C" void kernel_launch(void* const* d_in, const int* in_sizes, int n_in,
                              void* d_out, int out_size)
{
    const float* x    = (const float*)d_in[0];
    const float* pe   = (const float*)d_in[1];
    const float* Wqkv = (const float*)d_in[4];
    const float* bqkv = (const float*)d_in[5];
    const float* Wc   = (const float*)d_in[6];
    const float* bc   = (const float*)d_in[7];
    float* out = (float*)d_out;

    float *qkv, *attn;
    cudaGetSymbolAddress((void**)&qkv,  g_qkv);
    cudaGetSymbolAddress((void**)&attn, g_attn);

    // 1) qkv = (x + pe) @ Wqkv^T + bqkv   (4096 x 1536 x 512), tf32 HMMA
    gemm_mma<true><<<dim3(K3C_ / GBN, M_ / GBM), 256>>>(
        x, pe, Wqkv, bqkv, qkv, M_, K3C_, C_);

    // 2) causal attention -> g_attn
    attn_kernel<<<dim3(S_ / 32, B_, H_), 256>>>();

    // 3) out = attn @ Wc^T + bc           (4096 x 512 x 512), tf32 HMMA
    gemm_mma<false><<<dim3(C_ / GBN, M_ / GBM), 256>>>(
        attn, nullptr, Wc, bc, out, M_, C_, C_);
}

// round 6
// speedup vs baseline: 6.6341x; 2.3864x over previous
#include <cuda_runtime.h>
#include <cstdint>

#define S_   2048
#define B_   2
#define C_   512
#define H_   8
#define CC_  64
#define M_   (S_*B_)      // 4096
#define K3C_ (3*C_)       // 1536

// Scratch (static device globals — no dynamic allocation allowed)
__device__ float g_qkv[(size_t)M_ * K3C_];   // (s*B+b, 3C)
__device__ float g_attn[(size_t)M_ * C_];    // (s*B+b, C)

// ============================================================================
// tf32 helpers (portable PTX — no sm_103a-only instructions)
// ============================================================================
__device__ __forceinline__ uint32_t f2tf(float f) {
    uint32_t u;
    asm("cvt.rna.tf32.f32 %0, %1;" : "=r"(u) : "f"(f));
    return u;
}

__device__ __forceinline__ float ex2(float x) {
    float y;
    asm("ex2.approx.f32 %0, %1;" : "=f"(y) : "f"(x));
    return y;
}

__device__ __forceinline__ void mma_tf32(float c[4], const uint32_t a[4],
                                         const uint32_t b[2]) {
    asm volatile(
        "mma.sync.aligned.m16n8k8.row.col.f32.tf32.tf32.f32 "
        "{%0,%1,%2,%3}, {%4,%5,%6,%7}, {%8,%9}, {%0,%1,%2,%3};"
        : "+f"(c[0]), "+f"(c[1]), "+f"(c[2]), "+f"(c[3])
        : "r"(a[0]), "r"(a[1]), "r"(a[2]), "r"(a[3]), "r"(b[0]), "r"(b[1]));
}

// ============================================================================
// HMMA tf32 GEMM (NT): out[m][n] = sum_k (A[m][k](+A2[m][k])) * W[n][k] + b[n]
// BM=128, BN=128, BK=32. 8 warps as 2(m) x 4(n); warp tile 64x32.
// ============================================================================
#define GBM 128
#define GBN 128
#define GBK 32
#define GST 36   // smem row stride in floats (rows are 32 wide here)

template<bool ADD2>
__global__ void __launch_bounds__(256, 2)
gemm_mma(const float* __restrict__ A, const float* __restrict__ A2,
         const float* __restrict__ W, const float* __restrict__ bias,
         float* __restrict__ out, int Mdim, int Ndim, int Kdim)
{
    __shared__ uint32_t As[GBM * GST];
    __shared__ uint32_t Bs[GBN * GST];

    const int tid  = threadIdx.x;
    const int warp = tid >> 5;
    const int lane = tid & 31;
    const int g    = lane >> 2;
    const int tig  = lane & 3;
    const int wm   = warp & 1;
    const int wn   = warp >> 1;
    const int m0 = blockIdx.y * GBM;
    const int n0 = blockIdx.x * GBN;

    float acc[4][4][4] = {};

    for (int k0 = 0; k0 < Kdim; k0 += GBK) {
        __syncthreads();
        #pragma unroll
        for (int t = 0; t < 4; t++) {
            int idx = tid + t * 256;
            int r = idx >> 3, q = idx & 7;
            float4 va = *(const float4*)&A[(size_t)(m0 + r) * Kdim + k0 + q * 4];
            if (ADD2) {
                float4 v2 = *(const float4*)&A2[(size_t)(m0 + r) * Kdim + k0 + q * 4];
                va.x += v2.x; va.y += v2.y; va.z += v2.z; va.w += v2.w;
            }
            *(uint4*)&As[r * GST + q * 4] =
                make_uint4(f2tf(va.x), f2tf(va.y), f2tf(va.z), f2tf(va.w));
            float4 vb = *(const float4*)&W[(size_t)(n0 + r) * Kdim + k0 + q * 4];
            *(uint4*)&Bs[r * GST + q * 4] =
                make_uint4(f2tf(vb.x), f2tf(vb.y), f2tf(vb.z), f2tf(vb.w));
        }
        __syncthreads();

        #pragma unroll
        for (int ks = 0; ks < 4; ks++) {
            const int kb = ks * 8;
            uint32_t a[4][4], b[4][2];
            #pragma unroll
            for (int i = 0; i < 4; i++) {
                const int row = wm * 64 + i * 16;
                a[i][0] = As[(row + g)     * GST + kb + tig];
                a[i][1] = As[(row + g + 8) * GST + kb + tig];
                a[i][2] = As[(row + g)     * GST + kb + tig + 4];
                a[i][3] = As[(row + g + 8) * GST + kb + tig + 4];
            }
            #pragma unroll
            for (int j = 0; j < 4; j++) {
                const int col = wn * 32 + j * 8;
                b[j][0] = Bs[(col + g) * GST + kb + tig];
                b[j][1] = Bs[(col + g) * GST + kb + tig + 4];
            }
            #pragma unroll
            for (int i = 0; i < 4; i++)
                #pragma unroll
                for (int j = 0; j < 4; j++)
                    mma_tf32(acc[i][j], a[i], b[j]);
        }
    }

    #pragma unroll
    for (int i = 0; i < 4; i++) {
        const int row = m0 + wm * 64 + i * 16 + g;
        #pragma unroll
        for (int j = 0; j < 4; j++) {
            const int col = n0 + wn * 32 + j * 8 + 2 * tig;
            float2 bv = *(const float2*)&bias[col];
            float2 o0 = make_float2(acc[i][j][0] + bv.x, acc[i][j][1] + bv.y);
            float2 o1 = make_float2(acc[i][j][2] + bv.x, acc[i][j][3] + bv.y);
            *(float2*)&out[(size_t)row * Ndim + col]       = o0;
            *(float2*)&out[(size_t)(row + 8) * Ndim + col] = o1;
        }
    }
}

// ============================================================================
// Flash attention via HMMA tf32. Block = 64 queries x one (b,h); 4 warps x
// 16 rows. Q fragments live in registers (prescaled by 0.125*log2e); per
// 64-key tile: S = Q K^T (MMA), register online softmax (exp2 domain),
// P reuses the Ks buffer (K dead after S) -- warp w uses rows 16w..16w+15,
// then O += P V (MMA).
// Rows are 64 floats wide. K/Q/P stride 68 (mod32=4 -> frag banks 4g+tig,
// conflict-free); V stride 72 (mod32=8 -> frag banks 8*tig+g, conflict-free).
// Smem: 64*68*4 + 64*72*4 = 35840 B < 48 KB.
// ============================================================================
#define AST 68
#define VST 72
#define QSCALE 0.18033688f   // (1/sqrt(64)) * log2(e)

__global__ void __launch_bounds__(128)
attn_mma()
{
    __shared__ uint32_t Ks[64 * AST];   // K tile, then P tile (per-warp slices)
    __shared__ uint32_t Vs[64 * VST];

    const int tid  = threadIdx.x;
    const int warp = tid >> 5;
    const int lane = tid & 31;
    const int g    = lane >> 2;
    const int tig  = lane & 3;
    const int qt = (int)gridDim.x - 1 - (int)blockIdx.x;   // heavy blocks first
    const int q0 = qt * 64;
    const int b = blockIdx.y;
    const int h = blockIdx.z;
    const int rbase = warp * 16;

    // ---- Stage Q tile (prescaled, tf32) through Ks, lift into registers ----
    for (int i = tid; i < 64 * 16; i += 128) {
        int r = i >> 4, c4 = i & 15;
        float4 v = *(const float4*)&g_qkv[((size_t)(q0 + r) * B_ + b) * K3C_ + h * CC_ + c4 * 4];
        *(uint4*)&Ks[r * AST + c4 * 4] =
            make_uint4(f2tf(v.x * QSCALE), f2tf(v.y * QSCALE),
                       f2tf(v.z * QSCALE), f2tf(v.w * QSCALE));
    }
    __syncthreads();

    uint32_t qf[8][4];
    #pragma unroll
    for (int kb = 0; kb < 8; kb++) {
        qf[kb][0] = Ks[(rbase + g)     * AST + kb * 8 + tig];
        qf[kb][1] = Ks[(rbase + g + 8) * AST + kb * 8 + tig];
        qf[kb][2] = Ks[(rbase + g)     * AST + kb * 8 + tig + 4];
        qf[kb][3] = Ks[(rbase + g + 8) * AST + kb * 8 + tig + 4];
    }

    float o[8][4] = {};
    float m0 = -1e30f, m1 = -1e30f;
    float l0 = 0.0f,   l1 = 0.0f;

    for (int t0 = 0; t0 <= q0; t0 += 64) {
        __syncthreads();   // prior PV reads (Ks-as-P, Vs) complete
        // ---- cooperative K/V tile load (tf32 in smem) ----
        for (int i = tid; i < 64 * 16; i += 128) {
            int r = i >> 4, c4 = i & 15;
            size_t off = ((size_t)(t0 + r) * B_ + b) * K3C_ + h * CC_ + c4 * 4;
            float4 kv = *(const float4*)&g_qkv[off + C_];
            *(uint4*)&Ks[r * AST + c4 * 4] =
                make_uint4(f2tf(kv.x), f2tf(kv.y), f2tf(kv.z), f2tf(kv.w));
            float4 vv = *(const float4*)&g_qkv[off + 2 * C_];
            *(uint4*)&Vs[r * VST + c4 * 4] =
                make_uint4(f2tf(vv.x), f2tf(vv.y), f2tf(vv.z), f2tf(vv.w));
        }
        __syncthreads();

        // ---- S = Q K^T : 8 n-tiles x 8 k-steps ----
        float s[8][4];
        #pragma unroll
        for (int j = 0; j < 8; j++) { s[j][0] = s[j][1] = s[j][2] = s[j][3] = 0.0f; }
        #pragma unroll
        for (int kb = 0; kb < 8; kb++) {
            #pragma unroll
            for (int j = 0; j < 8; j++) {
                uint32_t bf[2];
                bf[0] = Ks[(j * 8 + g) * AST + kb * 8 + tig];
                bf[1] = Ks[(j * 8 + g) * AST + kb * 8 + tig + 4];
                mma_tf32(s[j], qf[kb], bf);
            }
        }

        // ---- causal mask (diagonal tile only) ----
        if (t0 == q0) {
            const int r0 = rbase + g;
            #pragma unroll
            for (int j = 0; j < 8; j++) {
                int t = j * 8 + 2 * tig;
                if (t     > r0)     s[j][0] = -1e30f;
                if (t + 1 > r0)     s[j][1] = -1e30f;
                if (t     > r0 + 8) s[j][2] = -1e30f;
                if (t + 1 > r0 + 8) s[j][3] = -1e30f;
            }
        }

        // ---- online softmax (scores already in log2 units) ----
        float a0 = -1e30f, a1 = -1e30f;
        #pragma unroll
        for (int j = 0; j < 8; j++) {
            a0 = fmaxf(a0, fmaxf(s[j][0], s[j][1]));
            a1 = fmaxf(a1, fmaxf(s[j][2], s[j][3]));
        }
        a0 = fmaxf(a0, __shfl_xor_sync(0xffffffffu, a0, 1));
        a0 = fmaxf(a0, __shfl_xor_sync(0xffffffffu, a0, 2));
        a1 = fmaxf(a1, __shfl_xor_sync(0xffffffffu, a1, 1));
        a1 = fmaxf(a1, __shfl_xor_sync(0xffffffffu, a1, 2));

        float mn0 = fmaxf(m0, a0);
        float mn1 = fmaxf(m1, a1);
        float sc0 = ex2(m0 - mn0);
        float sc1 = ex2(m1 - mn1);
        m0 = mn0; m1 = mn1;
        l0 *= sc0; l1 *= sc1;

        float p0[8], p1[8], p2[8], p3[8];
        #pragma unroll
        for (int j = 0; j < 8; j++) {
            // tf32-round p, accumulate l from the rounded values (matches PV)
            p0[j] = __uint_as_float(f2tf(ex2(s[j][0] - mn0)));
            p1[j] = __uint_as_float(f2tf(ex2(s[j][1] - mn0)));
            p2[j] = __uint_as_float(f2tf(ex2(s[j][2] - mn1)));
            p3[j] = __uint_as_float(f2tf(ex2(s[j][3] - mn1)));
            l0 += p0[j] + p1[j];
            l1 += p2[j] + p3[j];
            o[j][0] *= sc0; o[j][1] *= sc0; o[j][2] *= sc1; o[j][3] *= sc1;
        }

        // ---- stage P into this warp's Ks rows (K is dead after S) ----
        __syncthreads();   // all warps done reading Ks as K
        uint32_t* pw = Ks + rbase * AST;
        #pragma unroll
        for (int j = 0; j < 8; j++) {
            *(uint2*)&pw[(g)     * AST + j * 8 + 2 * tig] =
                make_uint2(__float_as_uint(p0[j]), __float_as_uint(p1[j]));
            *(uint2*)&pw[(g + 8) * AST + j * 8 + 2 * tig] =
                make_uint2(__float_as_uint(p2[j]), __float_as_uint(p3[j]));
        }
        __syncwarp();      // per-warp slice: warp-local visibility suffices

        // ---- O += P V : 8 k-steps (t) x 8 n-tiles (c) ----
        #pragma unroll
        for (int kt = 0; kt < 8; kt++) {
            uint32_t af[4];
            af[0] = pw[(g)     * AST + kt * 8 + tig];
            af[1] = pw[(g + 8) * AST + kt * 8 + tig];
            af[2] = pw[(g)     * AST + kt * 8 + tig + 4];
            af[3] = pw[(g + 8) * AST + kt * 8 + tig + 4];
            #pragma unroll
            for (int j = 0; j < 8; j++) {
                uint32_t bf[2];
                bf[0] = Vs[(kt * 8 + tig)     * VST + j * 8 + g];
                bf[1] = Vs[(kt * 8 + tig + 4) * VST + j * 8 + g];
                mma_tf32(o[j], af, bf);
            }
        }
    }

    // ---- normalize and store ----
    l0 += __shfl_xor_sync(0xffffffffu, l0, 1);
    l0 += __shfl_xor_sync(0xffffffffu, l0, 2);
    l1 += __shfl_xor_sync(0xffffffffu, l1, 1);
    l1 += __shfl_xor_sync(0xffffffffu, l1, 2);
    const float inv0 = 1.0f / l0;
    const float inv1 = 1.0f / l1;

    const int q_a = q0 + rbase + g;
    const int q_b = q_a + 8;
    #pragma unroll
    for (int j = 0; j < 8; j++) {
        const int col = h * CC_ + j * 8 + 2 * tig;
        *(float2*)&g_attn[((size_t)q_a * B_ + b) * C_ + col] =
            make_float2(o[j][0] * inv0, o[j][1] * inv0);
        *(float2*)&g_attn[((size_t)q_b * B_ + b) * C_ + col] =
            make_float2(o[j][2] * inv1, o[j][3] * inv1);
    }
}

// ============================================================================
// Inputs (metadata order): x, pe, content_mask, pad, Wqkv, bqkv, Wc, bc
// content_mask is strict-causal (t > s) -> applied analytically; pad unused.
// ============================================================================
extern "C" void kernel_launch(void* const* d_in, const int* in_sizes, int n_in,
                              void* d_out, int out_size)
{
    const float* x    = (const float*)d_in[0];
    const float* pe   = (const float*)d_in[1];
    const float* Wqkv = (const float*)d_in[4];
    const float* bqkv = (const float*)d_in[5];
    const float* Wc   = (const float*)d_in[6];
    const float* bc   = (const float*)d_in[7];
    float* out = (float*)d_out;

    float *qkv, *attn;
    cudaGetSymbolAddress((void**)&qkv,  g_qkv);
    cudaGetSymbolAddress((void**)&attn, g_attn);

    // 1) qkv = (x + pe) @ Wqkv^T + bqkv   (4096 x 1536 x 512), tf32 HMMA
    gemm_mma<true><<<dim3(K3C_ / GBN, M_ / GBM), 256>>>(
        x, pe, Wqkv, bqkv, qkv, M_, K3C_, C_);

    // 2) causal flash attention (tf32 HMMA) -> g_attn
    attn_mma<<<dim3(S_ / 64, B_, H_), 128>>>();

    // 3) out = attn @ Wc^T + bc           (4096 x 512 x 512), tf32 HMMA
    gemm_mma<false><<<dim3(C_ / GBN, M_ / GBM), 256>>>(
        attn, nullptr, Wc, bc, out, M_, C_, C_);
}

// round 7
// speedup vs baseline: 6.8731x; 1.0360x over previous
#include <cuda_runtime.h>
#include <cstdint>

#define S_   2048
#define B_   2
#define C_   512
#define H_   8
#define CC_  64
#define M_   (S_*B_)      // 4096
#define K3C_ (3*C_)       // 1536

// Scratch (static device globals — no dynamic allocation allowed)
__device__ float g_qkv[(size_t)M_ * K3C_];   // (s*B+b, 3C)
__device__ float g_attn[(size_t)M_ * C_];    // xpe scratch, then attn output

// ============================================================================
// helpers (portable PTX — no sm_103a-only instructions)
// ============================================================================
__device__ __forceinline__ uint32_t smem_u32(const void* p) {
    uint32_t a;
    asm("{ .reg .u64 t; cvta.to.shared.u64 t, %1; cvt.u32.u64 %0, t; }"
        : "=r"(a) : "l"(p));
    return a;
}

__device__ __forceinline__ uint32_t f2tf(float f) {
    uint32_t u;
    asm("cvt.rna.tf32.f32 %0, %1;" : "=r"(u) : "f"(f));
    return u;
}

__device__ __forceinline__ float ex2(float x) {
    float y;
    asm("ex2.approx.f32 %0, %1;" : "=f"(y) : "f"(x));
    return y;
}

__device__ __forceinline__ void mma_tf32(float c[4], const uint32_t a[4],
                                         const uint32_t b[2]) {
    asm volatile(
        "mma.sync.aligned.m16n8k8.row.col.f32.tf32.tf32.f32 "
        "{%0,%1,%2,%3}, {%4,%5,%6,%7}, {%8,%9}, {%0,%1,%2,%3};"
        : "+f"(c[0]), "+f"(c[1]), "+f"(c[2]), "+f"(c[3])
        : "r"(a[0]), "r"(a[1]), "r"(a[2]), "r"(a[3]), "r"(b[0]), "r"(b[1]));
}

__device__ __forceinline__ void cp_async16(uint32_t saddr, const void* gptr) {
    asm volatile("cp.async.cg.shared.global [%0], [%1], 16;"
                 :: "r"(saddr), "l"(gptr));
}
__device__ __forceinline__ void cp_commit() {
    asm volatile("cp.async.commit_group;");
}
template<int N>
__device__ __forceinline__ void cp_wait() {
    asm volatile("cp.async.wait_group %0;" :: "n"(N));
}

// ============================================================================
// x + pe -> g_attn (scratch), vectorized
// ============================================================================
__global__ void __launch_bounds__(256)
add_pe(const float4* __restrict__ x, const float4* __restrict__ pe,
       float4* __restrict__ out)
{
    int i = blockIdx.x * 256 + threadIdx.x;
    float4 a = x[i], p = pe[i];
    out[i] = make_float4(a.x + p.x, a.y + p.y, a.z + p.z, a.w + p.w);
}

// ============================================================================
// cp.async 2-stage pipelined HMMA tf32 GEMM (NT):
//   out[m][n] = sum_k A[m][k] * W[n][k] + bias[n]
// BM=BN=128, BK=32; 8 warps as 2(m) x 4(n), warp tile 64x32.
// Smem holds RAW fp32 (cp.async copies bytes); cvt->tf32 happens post-LDS.
// Dynamic smem: 2 stages x (A 128x36 + B 128x36) x 4B = 73728 B.
// ============================================================================
#define GBM 128
#define GBN 128
#define GBK 32
#define GST 36   // smem row stride (rows are 32 wide); 36*4=144 = 16B-aligned
#define GEMM_SMEM (2 * (GBM * GST + GBN * GST) * 4)

__global__ void __launch_bounds__(256, 2)
gemm_pipe(const float* __restrict__ A, const float* __restrict__ W,
          const float* __restrict__ bias, float* __restrict__ out,
          int Mdim, int Ndim, int Kdim)
{
    extern __shared__ uint32_t sm[];
    uint32_t* As = sm;                         // [2][GBM*GST]
    uint32_t* Bs = sm + 2 * GBM * GST;         // [2][GBN*GST]

    const int tid  = threadIdx.x;
    const int warp = tid >> 5;
    const int lane = tid & 31;
    const int g    = lane >> 2;
    const int tig  = lane & 3;
    const int wm   = warp & 1;
    const int wn   = warp >> 1;
    const int m0 = blockIdx.y * GBM;
    const int n0 = blockIdx.x * GBN;

    const uint32_t sA = smem_u32(As);
    const uint32_t sB = smem_u32(Bs);

    const int r_ld = tid >> 3;        // 0..31 (row group per 256-thread pass)
    const int q_ld = tid & 7;         // float4 index within 32-wide row

    // issue one K-chunk's loads into `stage`
    auto issue = [&](int stage, int k0) {
        const uint32_t offA = (uint32_t)(stage * GBM * GST) * 4;
        const uint32_t offB = (uint32_t)(stage * GBN * GST) * 4;
        #pragma unroll
        for (int t = 0; t < 4; t++) {
            int r = r_ld + t * 32;
            uint32_t so = (uint32_t)(r * GST + q_ld * 4) * 4;
            cp_async16(sA + offA + so, &A[(size_t)(m0 + r) * Kdim + k0 + q_ld * 4]);
            cp_async16(sB + offB + so, &W[(size_t)(n0 + r) * Kdim + k0 + q_ld * 4]);
        }
        cp_commit();
    };

    float acc[4][4][4] = {};
    const int NC = Kdim / GBK;

    issue(0, 0);

    for (int c = 0; c < NC; c++) {
        if (c + 1 < NC) issue((c + 1) & 1, (c + 1) * GBK);
        if (c + 1 < NC) cp_wait<1>(); else cp_wait<0>();
        __syncthreads();

        const uint32_t* Ac = As + (c & 1) * GBM * GST;
        const uint32_t* Bc = Bs + (c & 1) * GBN * GST;

        #pragma unroll
        for (int ks = 0; ks < 4; ks++) {
            const int kb = ks * 8;
            uint32_t a[4][4], b[4][2];
            #pragma unroll
            for (int i = 0; i < 4; i++) {
                const int row = wm * 64 + i * 16;
                a[i][0] = f2tf(__uint_as_float(Ac[(row + g)     * GST + kb + tig]));
                a[i][1] = f2tf(__uint_as_float(Ac[(row + g + 8) * GST + kb + tig]));
                a[i][2] = f2tf(__uint_as_float(Ac[(row + g)     * GST + kb + tig + 4]));
                a[i][3] = f2tf(__uint_as_float(Ac[(row + g + 8) * GST + kb + tig + 4]));
            }
            #pragma unroll
            for (int j = 0; j < 4; j++) {
                const int col = wn * 32 + j * 8;
                b[j][0] = f2tf(__uint_as_float(Bc[(col + g) * GST + kb + tig]));
                b[j][1] = f2tf(__uint_as_float(Bc[(col + g) * GST + kb + tig + 4]));
            }
            #pragma unroll
            for (int i = 0; i < 4; i++)
                #pragma unroll
                for (int j = 0; j < 4; j++)
                    mma_tf32(acc[i][j], a[i], b[j]);
        }
        __syncthreads();   // all warps done with stage (c&1) before re-issue
    }

    #pragma unroll
    for (int i = 0; i < 4; i++) {
        const int row = m0 + wm * 64 + i * 16 + g;
        #pragma unroll
        for (int j = 0; j < 4; j++) {
            const int col = n0 + wn * 32 + j * 8 + 2 * tig;
            float2 bv = *(const float2*)&bias[col];
            float2 o0 = make_float2(acc[i][j][0] + bv.x, acc[i][j][1] + bv.y);
            float2 o1 = make_float2(acc[i][j][2] + bv.x, acc[i][j][3] + bv.y);
            *(float2*)&out[(size_t)row * Ndim + col]       = o0;
            *(float2*)&out[(size_t)(row + 8) * Ndim + col] = o1;
        }
    }
}

// ============================================================================
// Flash attention via HMMA tf32 (unchanged from R6, passing at ~107us).
// Block = 64 queries x one (b,h); 4 warps x 16 rows. P reuses Ks buffer.
// K/Q/P stride 68, V stride 72 -> conflict-free fragment LDS.
// ============================================================================
#define AST 68
#define VST 72
#define QSCALE 0.18033688f   // (1/sqrt(64)) * log2(e)

__global__ void __launch_bounds__(128)
attn_mma()
{
    __shared__ uint32_t Ks[64 * AST];   // K tile, then P tile (per-warp slices)
    __shared__ uint32_t Vs[64 * VST];

    const int tid  = threadIdx.x;
    const int warp = tid >> 5;
    const int lane = tid & 31;
    const int g    = lane >> 2;
    const int tig  = lane & 3;
    const int qt = (int)gridDim.x - 1 - (int)blockIdx.x;   // heavy blocks first
    const int q0 = qt * 64;
    const int b = blockIdx.y;
    const int h = blockIdx.z;
    const int rbase = warp * 16;

    // ---- Stage Q tile (prescaled, tf32) through Ks, lift into registers ----
    for (int i = tid; i < 64 * 16; i += 128) {
        int r = i >> 4, c4 = i & 15;
        float4 v = *(const float4*)&g_qkv[((size_t)(q0 + r) * B_ + b) * K3C_ + h * CC_ + c4 * 4];
        *(uint4*)&Ks[r * AST + c4 * 4] =
            make_uint4(f2tf(v.x * QSCALE), f2tf(v.y * QSCALE),
                       f2tf(v.z * QSCALE), f2tf(v.w * QSCALE));
    }
    __syncthreads();

    uint32_t qf[8][4];
    #pragma unroll
    for (int kb = 0; kb < 8; kb++) {
        qf[kb][0] = Ks[(rbase + g)     * AST + kb * 8 + tig];
        qf[kb][1] = Ks[(rbase + g + 8) * AST + kb * 8 + tig];
        qf[kb][2] = Ks[(rbase + g)     * AST + kb * 8 + tig + 4];
        qf[kb][3] = Ks[(rbase + g + 8) * AST + kb * 8 + tig + 4];
    }

    float o[8][4] = {};
    float m0 = -1e30f, m1 = -1e30f;
    float l0 = 0.0f,   l1 = 0.0f;

    for (int t0 = 0; t0 <= q0; t0 += 64) {
        __syncthreads();   // prior PV reads (Ks-as-P, Vs) complete
        for (int i = tid; i < 64 * 16; i += 128) {
            int r = i >> 4, c4 = i & 15;
            size_t off = ((size_t)(t0 + r) * B_ + b) * K3C_ + h * CC_ + c4 * 4;
            float4 kv = *(const float4*)&g_qkv[off + C_];
            *(uint4*)&Ks[r * AST + c4 * 4] =
                make_uint4(f2tf(kv.x), f2tf(kv.y), f2tf(kv.z), f2tf(kv.w));
            float4 vv = *(const float4*)&g_qkv[off + 2 * C_];
            *(uint4*)&Vs[r * VST + c4 * 4] =
                make_uint4(f2tf(vv.x), f2tf(vv.y), f2tf(vv.z), f2tf(vv.w));
        }
        __syncthreads();

        // ---- S = Q K^T ----
        float s[8][4];
        #pragma unroll
        for (int j = 0; j < 8; j++) { s[j][0] = s[j][1] = s[j][2] = s[j][3] = 0.0f; }
        #pragma unroll
        for (int kb = 0; kb < 8; kb++) {
            #pragma unroll
            for (int j = 0; j < 8; j++) {
                uint32_t bf[2];
                bf[0] = Ks[(j * 8 + g) * AST + kb * 8 + tig];
                bf[1] = Ks[(j * 8 + g) * AST + kb * 8 + tig + 4];
                mma_tf32(s[j], qf[kb], bf);
            }
        }

        // ---- causal mask (diagonal tile only) ----
        if (t0 == q0) {
            const int r0 = rbase + g;
            #pragma unroll
            for (int j = 0; j < 8; j++) {
                int t = j * 8 + 2 * tig;
                if (t     > r0)     s[j][0] = -1e30f;
                if (t + 1 > r0)     s[j][1] = -1e30f;
                if (t     > r0 + 8) s[j][2] = -1e30f;
                if (t + 1 > r0 + 8) s[j][3] = -1e30f;
            }
        }

        // ---- online softmax (exp2 domain) ----
        float a0 = -1e30f, a1 = -1e30f;
        #pragma unroll
        for (int j = 0; j < 8; j++) {
            a0 = fmaxf(a0, fmaxf(s[j][0], s[j][1]));
            a1 = fmaxf(a1, fmaxf(s[j][2], s[j][3]));
        }
        a0 = fmaxf(a0, __shfl_xor_sync(0xffffffffu, a0, 1));
        a0 = fmaxf(a0, __shfl_xor_sync(0xffffffffu, a0, 2));
        a1 = fmaxf(a1, __shfl_xor_sync(0xffffffffu, a1, 1));
        a1 = fmaxf(a1, __shfl_xor_sync(0xffffffffu, a1, 2));

        float mn0 = fmaxf(m0, a0);
        float mn1 = fmaxf(m1, a1);
        float sc0 = ex2(m0 - mn0);
        float sc1 = ex2(m1 - mn1);
        m0 = mn0; m1 = mn1;
        l0 *= sc0; l1 *= sc1;

        float p0[8], p1[8], p2[8], p3[8];
        #pragma unroll
        for (int j = 0; j < 8; j++) {
            p0[j] = __uint_as_float(f2tf(ex2(s[j][0] - mn0)));
            p1[j] = __uint_as_float(f2tf(ex2(s[j][1] - mn0)));
            p2[j] = __uint_as_float(f2tf(ex2(s[j][2] - mn1)));
            p3[j] = __uint_as_float(f2tf(ex2(s[j][3] - mn1)));
            l0 += p0[j] + p1[j];
            l1 += p2[j] + p3[j];
            o[j][0] *= sc0; o[j][1] *= sc0; o[j][2] *= sc1; o[j][3] *= sc1;
        }

        // ---- stage P into this warp's Ks rows (K dead after S) ----
        __syncthreads();
        uint32_t* pw = Ks + rbase * AST;
        #pragma unroll
        for (int j = 0; j < 8; j++) {
            *(uint2*)&pw[(g)     * AST + j * 8 + 2 * tig] =
                make_uint2(__float_as_uint(p0[j]), __float_as_uint(p1[j]));
            *(uint2*)&pw[(g + 8) * AST + j * 8 + 2 * tig] =
                make_uint2(__float_as_uint(p2[j]), __float_as_uint(p3[j]));
        }
        __syncwarp();

        // ---- O += P V ----
        #pragma unroll
        for (int kt = 0; kt < 8; kt++) {
            uint32_t af[4];
            af[0] = pw[(g)     * AST + kt * 8 + tig];
            af[1] = pw[(g + 8) * AST + kt * 8 + tig];
            af[2] = pw[(g)     * AST + kt * 8 + tig + 4];
            af[3] = pw[(g + 8) * AST + kt * 8 + tig + 4];
            #pragma unroll
            for (int j = 0; j < 8; j++) {
                uint32_t bf[2];
                bf[0] = Vs[(kt * 8 + tig)     * VST + j * 8 + g];
                bf[1] = Vs[(kt * 8 + tig + 4) * VST + j * 8 + g];
                mma_tf32(o[j], af, bf);
            }
        }
    }

    // ---- normalize and store ----
    l0 += __shfl_xor_sync(0xffffffffu, l0, 1);
    l0 += __shfl_xor_sync(0xffffffffu, l0, 2);
    l1 += __shfl_xor_sync(0xffffffffu, l1, 1);
    l1 += __shfl_xor_sync(0xffffffffu, l1, 2);
    const float inv0 = 1.0f / l0;
    const float inv1 = 1.0f / l1;

    const int q_a = q0 + rbase + g;
    const int q_b = q_a + 8;
    #pragma unroll
    for (int j = 0; j < 8; j++) {
        const int col = h * CC_ + j * 8 + 2 * tig;
        *(float2*)&g_attn[((size_t)q_a * B_ + b) * C_ + col] =
            make_float2(o[j][0] * inv0, o[j][1] * inv0);
        *(float2*)&g_attn[((size_t)q_b * B_ + b) * C_ + col] =
            make_float2(o[j][2] * inv1, o[j][3] * inv1);
    }
}

// ============================================================================
// Inputs (metadata order): x, pe, content_mask, pad, Wqkv, bqkv, Wc, bc
// content_mask is strict-causal (t > s) -> applied analytically; pad unused.
// Sequence: xpe=g_attn -> GEMM1(A=g_attn)->g_qkv -> attn overwrites g_attn
//           -> GEMM3(A=g_attn)->out.
// ============================================================================
extern "C" void kernel_launch(void* const* d_in, const int* in_sizes, int n_in,
                              void* d_out, int out_size)
{
    const float* x    = (const float*)d_in[0];
    const float* pe   = (const float*)d_in[1];
    const float* Wqkv = (const float*)d_in[4];
    const float* bqkv = (const float*)d_in[5];
    const float* Wc   = (const float*)d_in[6];
    const float* bc   = (const float*)d_in[7];
    float* out = (float*)d_out;

    float *qkv, *attn;
    cudaGetSymbolAddress((void**)&qkv,  g_qkv);
    cudaGetSymbolAddress((void**)&attn, g_attn);

    cudaFuncSetAttribute(gemm_pipe,
                         cudaFuncAttributeMaxDynamicSharedMemorySize, GEMM_SMEM);

    // 0) xpe = x + pe  (into g_attn scratch)
    add_pe<<<(M_ * C_ / 4) / 256, 256>>>(
        (const float4*)x, (const float4*)pe, (float4*)attn);

    // 1) qkv = xpe @ Wqkv^T + bqkv   (4096 x 1536 x 512)
    gemm_pipe<<<dim3(K3C_ / GBN, M_ / GBM), 256, GEMM_SMEM>>>(
        attn, Wqkv, bqkv, qkv, M_, K3C_, C_);

    // 2) causal flash attention (tf32 HMMA) -> g_attn
    attn_mma<<<dim3(S_ / 64, B_, H_), 128>>>();

    // 3) out = attn @ Wc^T + bc      (4096 x 512 x 512)
    gemm_pipe<<<dim3(C_ / GBN, M_ / GBM), 256, GEMM_SMEM>>>(
        attn, Wc, bc, out, M_, C_, C_);
}

// round 8
// speedup vs baseline: 8.4452x; 1.2287x over previous
#include <cuda_runtime.h>
#include <cstdint>

#define S_   2048
#define B_   2
#define C_   512
#define H_   8
#define CC_  64
#define M_   (S_*B_)      // 4096
#define K3C_ (3*C_)       // 1536

// Scratch (static device globals — no dynamic allocation allowed)
__device__ float g_qkv[(size_t)M_ * K3C_];   // (s*B+b, 3C)
__device__ float g_attn[(size_t)M_ * C_];    // xpe scratch, then attn output

// ============================================================================
// helpers (portable PTX — no sm_103a-only instructions)
// ============================================================================
__device__ __forceinline__ uint32_t smem_u32(const void* p) {
    uint32_t a;
    asm("{ .reg .u64 t; cvta.to.shared.u64 t, %1; cvt.u32.u64 %0, t; }"
        : "=r"(a) : "l"(p));
    return a;
}

__device__ __forceinline__ uint32_t f2tf(float f) {
    uint32_t u;
    asm("cvt.rna.tf32.f32 %0, %1;" : "=r"(u) : "f"(f));
    return u;
}

__device__ __forceinline__ float ex2(float x) {
    float y;
    asm("ex2.approx.f32 %0, %1;" : "=f"(y) : "f"(x));
    return y;
}

__device__ __forceinline__ void mma_tf32(float c[4], const uint32_t a[4],
                                         const uint32_t b[2]) {
    asm volatile(
        "mma.sync.aligned.m16n8k8.row.col.f32.tf32.tf32.f32 "
        "{%0,%1,%2,%3}, {%4,%5,%6,%7}, {%8,%9}, {%0,%1,%2,%3};"
        : "+f"(c[0]), "+f"(c[1]), "+f"(c[2]), "+f"(c[3])
        : "r"(a[0]), "r"(a[1]), "r"(a[2]), "r"(a[3]), "r"(b[0]), "r"(b[1]));
}

__device__ __forceinline__ void cp_async16(uint32_t saddr, const void* gptr) {
    asm volatile("cp.async.cg.shared.global [%0], [%1], 16;"
                 :: "r"(saddr), "l"(gptr));
}
__device__ __forceinline__ void cp_commit() {
    asm volatile("cp.async.commit_group;");
}
template<int N>
__device__ __forceinline__ void cp_wait() {
    asm volatile("cp.async.wait_group %0;" :: "n"(N));
}

// ============================================================================
// x + pe -> g_attn (scratch), vectorized
// ============================================================================
__global__ void __launch_bounds__(256)
add_pe(const float4* __restrict__ x, const float4* __restrict__ pe,
       float4* __restrict__ out)
{
    int i = blockIdx.x * 256 + threadIdx.x;
    float4 a = x[i], p = pe[i];
    out[i] = make_float4(a.x + p.x, a.y + p.y, a.z + p.z, a.w + p.w);
}

// ============================================================================
// cp.async 2-stage pipelined HMMA tf32 GEMM (NT) — unchanged from R7.
// ============================================================================
#define GBM 128
#define GBN 128
#define GBK 32
#define GST 36
#define GEMM_SMEM (2 * (GBM * GST + GBN * GST) * 4)

__global__ void __launch_bounds__(256, 2)
gemm_pipe(const float* __restrict__ A, const float* __restrict__ W,
          const float* __restrict__ bias, float* __restrict__ out,
          int Mdim, int Ndim, int Kdim)
{
    extern __shared__ uint32_t sm[];
    uint32_t* As = sm;
    uint32_t* Bs = sm + 2 * GBM * GST;

    const int tid  = threadIdx.x;
    const int warp = tid >> 5;
    const int lane = tid & 31;
    const int g    = lane >> 2;
    const int tig  = lane & 3;
    const int wm   = warp & 1;
    const int wn   = warp >> 1;
    const int m0 = blockIdx.y * GBM;
    const int n0 = blockIdx.x * GBN;

    const uint32_t sA = smem_u32(As);
    const uint32_t sB = smem_u32(Bs);

    const int r_ld = tid >> 3;
    const int q_ld = tid & 7;

    auto issue = [&](int stage, int k0) {
        const uint32_t offA = (uint32_t)(stage * GBM * GST) * 4;
        const uint32_t offB = (uint32_t)(stage * GBN * GST) * 4;
        #pragma unroll
        for (int t = 0; t < 4; t++) {
            int r = r_ld + t * 32;
            uint32_t so = (uint32_t)(r * GST + q_ld * 4) * 4;
            cp_async16(sA + offA + so, &A[(size_t)(m0 + r) * Kdim + k0 + q_ld * 4]);
            cp_async16(sB + offB + so, &W[(size_t)(n0 + r) * Kdim + k0 + q_ld * 4]);
        }
        cp_commit();
    };

    float acc[4][4][4] = {};
    const int NC = Kdim / GBK;

    issue(0, 0);

    for (int c = 0; c < NC; c++) {
        if (c + 1 < NC) issue((c + 1) & 1, (c + 1) * GBK);
        if (c + 1 < NC) cp_wait<1>(); else cp_wait<0>();
        __syncthreads();

        const uint32_t* Ac = As + (c & 1) * GBM * GST;
        const uint32_t* Bc = Bs + (c & 1) * GBN * GST;

        #pragma unroll
        for (int ks = 0; ks < 4; ks++) {
            const int kb = ks * 8;
            uint32_t a[4][4], b[4][2];
            #pragma unroll
            for (int i = 0; i < 4; i++) {
                const int row = wm * 64 + i * 16;
                a[i][0] = f2tf(__uint_as_float(Ac[(row + g)     * GST + kb + tig]));
                a[i][1] = f2tf(__uint_as_float(Ac[(row + g + 8) * GST + kb + tig]));
                a[i][2] = f2tf(__uint_as_float(Ac[(row + g)     * GST + kb + tig + 4]));
                a[i][3] = f2tf(__uint_as_float(Ac[(row + g + 8) * GST + kb + tig + 4]));
            }
            #pragma unroll
            for (int j = 0; j < 4; j++) {
                const int col = wn * 32 + j * 8;
                b[j][0] = f2tf(__uint_as_float(Bc[(col + g) * GST + kb + tig]));
                b[j][1] = f2tf(__uint_as_float(Bc[(col + g) * GST + kb + tig + 4]));
            }
            #pragma unroll
            for (int i = 0; i < 4; i++)
                #pragma unroll
                for (int j = 0; j < 4; j++)
                    mma_tf32(acc[i][j], a[i], b[j]);
        }
        __syncthreads();
    }

    #pragma unroll
    for (int i = 0; i < 4; i++) {
        const int row = m0 + wm * 64 + i * 16 + g;
        #pragma unroll
        for (int j = 0; j < 4; j++) {
            const int col = n0 + wn * 32 + j * 8 + 2 * tig;
            float2 bv = *(const float2*)&bias[col];
            float2 o0 = make_float2(acc[i][j][0] + bv.x, acc[i][j][1] + bv.y);
            float2 o1 = make_float2(acc[i][j][2] + bv.x, acc[i][j][3] + bv.y);
            *(float2*)&out[(size_t)row * Ndim + col]       = o0;
            *(float2*)&out[(size_t)(row + 8) * Ndim + col] = o1;
        }
    }
}

// ============================================================================
// Flash attention via HMMA tf32 with cp.async 2-stage K/V double buffering.
// Block = 64 queries x one (b,h); 4 warps x 16 rows. Raw fp32 in smem;
// cvt->tf32 at fragment load. P (tf32) reuses current-stage K buffer.
// K/Q/P stride 68, V stride 72 -> conflict-free fragment LDS.
// Dynamic smem: 2*(64*68 + 64*72)*4 = 71680 B.
// ============================================================================
#define AST 68
#define VST 72
#define KTILE (64 * AST)
#define VTILE (64 * VST)
#define ATT_SMEM (2 * (KTILE + VTILE) * 4)
#define QSCALE 0.18033688f   // (1/sqrt(64)) * log2(e)

__global__ void __launch_bounds__(128)
attn_mma()
{
    extern __shared__ uint32_t sm[];
    uint32_t* Ks = sm;                 // [2][KTILE]
    uint32_t* Vs = sm + 2 * KTILE;     // [2][VTILE]

    const int tid  = threadIdx.x;
    const int warp = tid >> 5;
    const int lane = tid & 31;
    const int g    = lane >> 2;
    const int tig  = lane & 3;
    const int qt = (int)gridDim.x - 1 - (int)blockIdx.x;   // heavy blocks first
    const int q0 = qt * 64;
    const int b = blockIdx.y;
    const int h = blockIdx.z;
    const int rbase = warp * 16;

    const uint32_t sK = smem_u32(Ks);
    const uint32_t sV = smem_u32(Vs);

    // issue one 64-key K/V tile into `stage`
    auto issue = [&](int stage, int t0) {
        const uint32_t kb = sK + (uint32_t)(stage * KTILE) * 4;
        const uint32_t vb = sV + (uint32_t)(stage * VTILE) * 4;
        #pragma unroll
        for (int i = tid; i < 64 * 16; i += 128) {
            int r = i >> 4, c4 = i & 15;
            const float* gp = &g_qkv[((size_t)(t0 + r) * B_ + b) * K3C_ + h * CC_ + c4 * 4];
            cp_async16(kb + (uint32_t)(r * AST + c4 * 4) * 4, gp + C_);
            cp_async16(vb + (uint32_t)(r * VST + c4 * 4) * 4, gp + 2 * C_);
        }
        cp_commit();
    };

    // prefetch tile 0 into stage 0
    issue(0, 0);

    // ---- Stage Q (prescaled, tf32) through stage-1 K area, lift to regs ----
    uint32_t* Qst = Ks + KTILE;
    for (int i = tid; i < 64 * 16; i += 128) {
        int r = i >> 4, c4 = i & 15;
        float4 v = *(const float4*)&g_qkv[((size_t)(q0 + r) * B_ + b) * K3C_ + h * CC_ + c4 * 4];
        *(uint4*)&Qst[r * AST + c4 * 4] =
            make_uint4(f2tf(v.x * QSCALE), f2tf(v.y * QSCALE),
                       f2tf(v.z * QSCALE), f2tf(v.w * QSCALE));
    }
    __syncthreads();

    uint32_t qf[8][4];
    #pragma unroll
    for (int kb = 0; kb < 8; kb++) {
        qf[kb][0] = Qst[(rbase + g)     * AST + kb * 8 + tig];
        qf[kb][1] = Qst[(rbase + g + 8) * AST + kb * 8 + tig];
        qf[kb][2] = Qst[(rbase + g)     * AST + kb * 8 + tig + 4];
        qf[kb][3] = Qst[(rbase + g + 8) * AST + kb * 8 + tig + 4];
    }

    float o[8][4] = {};
    float m0 = -1e30f, m1 = -1e30f;
    float l0 = 0.0f,   l1 = 0.0f;

    const int ntiles = qt + 1;
    for (int ti = 0; ti < ntiles; ti++) {
        const int cur = ti & 1;
        cp_wait<0>();
        __syncthreads();   // tile `ti` resident; prior stage reads complete
        if (ti + 1 < ntiles) issue(cur ^ 1, (ti + 1) * 64);

        const uint32_t* Kc = Ks + cur * KTILE;
        const uint32_t* Vc = Vs + cur * VTILE;

        // ---- S = Q K^T ----
        float s[8][4];
        #pragma unroll
        for (int j = 0; j < 8; j++) { s[j][0] = s[j][1] = s[j][2] = s[j][3] = 0.0f; }
        #pragma unroll
        for (int kb = 0; kb < 8; kb++) {
            #pragma unroll
            for (int j = 0; j < 8; j++) {
                uint32_t bf[2];
                bf[0] = f2tf(__uint_as_float(Kc[(j * 8 + g) * AST + kb * 8 + tig]));
                bf[1] = f2tf(__uint_as_float(Kc[(j * 8 + g) * AST + kb * 8 + tig + 4]));
                mma_tf32(s[j], qf[kb], bf);
            }
        }

        // ---- causal mask (diagonal tile only) ----
        if (ti == ntiles - 1) {
            const int r0 = rbase + g;
            #pragma unroll
            for (int j = 0; j < 8; j++) {
                int t = j * 8 + 2 * tig;
                if (t     > r0)     s[j][0] = -1e30f;
                if (t + 1 > r0)     s[j][1] = -1e30f;
                if (t     > r0 + 8) s[j][2] = -1e30f;
                if (t + 1 > r0 + 8) s[j][3] = -1e30f;
            }
        }

        // ---- online softmax (exp2 domain) ----
        float a0 = -1e30f, a1 = -1e30f;
        #pragma unroll
        for (int j = 0; j < 8; j++) {
            a0 = fmaxf(a0, fmaxf(s[j][0], s[j][1]));
            a1 = fmaxf(a1, fmaxf(s[j][2], s[j][3]));
        }
        a0 = fmaxf(a0, __shfl_xor_sync(0xffffffffu, a0, 1));
        a0 = fmaxf(a0, __shfl_xor_sync(0xffffffffu, a0, 2));
        a1 = fmaxf(a1, __shfl_xor_sync(0xffffffffu, a1, 1));
        a1 = fmaxf(a1, __shfl_xor_sync(0xffffffffu, a1, 2));

        float mn0 = fmaxf(m0, a0);
        float mn1 = fmaxf(m1, a1);
        float sc0 = ex2(m0 - mn0);
        float sc1 = ex2(m1 - mn1);
        m0 = mn0; m1 = mn1;
        l0 *= sc0; l1 *= sc1;

        float p0[8], p1[8], p2[8], p3[8];
        #pragma unroll
        for (int j = 0; j < 8; j++) {
            p0[j] = __uint_as_float(f2tf(ex2(s[j][0] - mn0)));
            p1[j] = __uint_as_float(f2tf(ex2(s[j][1] - mn0)));
            p2[j] = __uint_as_float(f2tf(ex2(s[j][2] - mn1)));
            p3[j] = __uint_as_float(f2tf(ex2(s[j][3] - mn1)));
            l0 += p0[j] + p1[j];
            l1 += p2[j] + p3[j];
            o[j][0] *= sc0; o[j][1] *= sc0; o[j][2] *= sc1; o[j][3] *= sc1;
        }

        // ---- stage P (tf32) into this warp's rows of current K buffer ----
        __syncthreads();   // all warps done reading Kc as K
        uint32_t* pw = (uint32_t*)Kc + rbase * AST;
        #pragma unroll
        for (int j = 0; j < 8; j++) {
            *(uint2*)&pw[(g)     * AST + j * 8 + 2 * tig] =
                make_uint2(__float_as_uint(p0[j]), __float_as_uint(p1[j]));
            *(uint2*)&pw[(g + 8) * AST + j * 8 + 2 * tig] =
                make_uint2(__float_as_uint(p2[j]), __float_as_uint(p3[j]));
        }
        __syncwarp();

        // ---- O += P V ----
        #pragma unroll
        for (int kt = 0; kt < 8; kt++) {
            uint32_t af[4];
            af[0] = pw[(g)     * AST + kt * 8 + tig];
            af[1] = pw[(g + 8) * AST + kt * 8 + tig];
            af[2] = pw[(g)     * AST + kt * 8 + tig + 4];
            af[3] = pw[(g + 8) * AST + kt * 8 + tig + 4];
            #pragma unroll
            for (int j = 0; j < 8; j++) {
                uint32_t bf[2];
                bf[0] = f2tf(__uint_as_float(Vc[(kt * 8 + tig)     * VST + j * 8 + g]));
                bf[1] = f2tf(__uint_as_float(Vc[(kt * 8 + tig + 4) * VST + j * 8 + g]));
                mma_tf32(o[j], af, bf);
            }
        }
    }

    // ---- normalize and store ----
    l0 += __shfl_xor_sync(0xffffffffu, l0, 1);
    l0 += __shfl_xor_sync(0xffffffffu, l0, 2);
    l1 += __shfl_xor_sync(0xffffffffu, l1, 1);
    l1 += __shfl_xor_sync(0xffffffffu, l1, 2);
    const float inv0 = 1.0f / l0;
    const float inv1 = 1.0f / l1;

    const int q_a = q0 + rbase + g;
    const int q_b = q_a + 8;
    #pragma unroll
    for (int j = 0; j < 8; j++) {
        const int col = h * CC_ + j * 8 + 2 * tig;
        *(float2*)&g_attn[((size_t)q_a * B_ + b) * C_ + col] =
            make_float2(o[j][0] * inv0, o[j][1] * inv0);
        *(float2*)&g_attn[((size_t)q_b * B_ + b) * C_ + col] =
            make_float2(o[j][2] * inv1, o[j][3] * inv1);
    }
}

// ============================================================================
// Inputs (metadata order): x, pe, content_mask, pad, Wqkv, bqkv, Wc, bc
// content_mask is strict-causal (t > s) -> applied analytically; pad unused.
// ============================================================================
extern "C" void kernel_launch(void* const* d_in, const int* in_sizes, int n_in,
                              void* d_out, int out_size)
{
    const float* x    = (const float*)d_in[0];
    const float* pe   = (const float*)d_in[1];
    const float* Wqkv = (const float*)d_in[4];
    const float* bqkv = (const float*)d_in[5];
    const float* Wc   = (const float*)d_in[6];
    const float* bc   = (const float*)d_in[7];
    float* out = (float*)d_out;

    float *qkv, *attn;
    cudaGetSymbolAddress((void**)&qkv,  g_qkv);
    cudaGetSymbolAddress((void**)&attn, g_attn);

    cudaFuncSetAttribute(gemm_pipe,
                         cudaFuncAttributeMaxDynamicSharedMemorySize, GEMM_SMEM);
    cudaFuncSetAttribute(attn_mma,
                         cudaFuncAttributeMaxDynamicSharedMemorySize, ATT_SMEM);

    // 0) xpe = x + pe  (into g_attn scratch)
    add_pe<<<(M_ * C_ / 4) / 256, 256>>>(
        (const float4*)x, (const float4*)pe, (float4*)attn);

    // 1) qkv = xpe @ Wqkv^T + bqkv   (4096 x 1536 x 512)
    gemm_pipe<<<dim3(K3C_ / GBN, M_ / GBM), 256, GEMM_SMEM>>>(
        attn, Wqkv, bqkv, qkv, M_, K3C_, C_);

    // 2) causal flash attention (tf32 HMMA, cp.async pipelined) -> g_attn
    attn_mma<<<dim3(S_ / 64, B_, H_), 128, ATT_SMEM>>>();

    // 3) out = attn @ Wc^T + bc      (4096 x 512 x 512)
    gemm_pipe<<<dim3(C_ / GBN, M_ / GBM), 256, GEMM_SMEM>>>(
        attn, Wc, bc, out, M_, C_, C_);
}